// round 16
// baseline (speedup 1.0000x reference)
#include <cuda_runtime.h>

#define NN 50000
#define EE 800000

typedef unsigned long long u64;

// ---------------- scratch (device globals; no allocation allowed) ----------
__device__ float g_SQa[NN * 2];
__device__ float g_SKa[NN * 2];
__device__ float g_SQb[NN * 2];
__device__ float g_SKb[NN * 2];
__device__ float g_vpa[NN * 64];
__device__ float g_vpb[NN * 64];
__device__ float g_sa[NN * 2];
__device__ float g_sb[NN * 2];
__device__ float g_agga[NN * 64];
__device__ float g_aggb[NN * 64];
// CSR + permuted edge data
__device__ int g_cnt1[NN];
__device__ int g_cnt2[NN];
__device__ int g_offs1[NN + 1];
__device__ int g_offs2[NN + 1];
__device__ int g_pos1[NN];
__device__ int g_pos2[NN];
__device__ int g_rowp1[EE];
__device__ int g_rowp2[EE];
__device__ float g_eap1[(size_t)EE * 16];
__device__ float g_eap2[(size_t)EE * 16];

__device__ __forceinline__ float tanh_h(float x) {
    float y;
    asm("tanh.approx.f32 %0, %1;" : "=f"(y) : "f"(x));
    return y;
}
__device__ __forceinline__ u64 pack2(float a, float b) {
    u64 r;
    asm("mov.b64 %0, {%1, %2};" : "=l"(r) : "f"(a), "f"(b));
    return r;
}
__device__ __forceinline__ void unpack2(u64 v, float& a, float& b) {
    asm("mov.b64 {%0, %1}, %2;" : "=f"(a), "=f"(b) : "l"(v));
}
__device__ __forceinline__ void ffma2(u64& d, u64 a, u64 b) {
    asm("fma.rn.f32x2 %0, %1, %2, %3;" : "=l"(d) : "l"(a), "l"(b), "l"(d));
}
__device__ __forceinline__ u64 mul2(u64 a, u64 b) {
    u64 r;
    asm("mul.rn.f32x2 %0, %1, %2;" : "=l"(r) : "l"(a), "l"(b));
    return r;
}

// ---------------- CSR build ------------------------------------------------
__global__ void __launch_bounds__(256) hist_kernel(
    const int* __restrict__ col1, const int* __restrict__ col2)
{
    int r_sel = blockIdx.x & 1;
    const int* col = r_sel ? col2 : col1;
    int* cnt = r_sel ? g_cnt2 : g_cnt1;
    int stride = (gridDim.x >> 1) * blockDim.x;
    for (int e = (blockIdx.x >> 1) * blockDim.x + threadIdx.x; e < EE; e += stride)
        atomicAdd(&cnt[__ldg(col + e)], 1);
}

__global__ void __launch_bounds__(1024) scan_kernel()
{
    const int* cnt = blockIdx.x ? g_cnt2 : g_cnt1;
    int* offs = blockIdx.x ? g_offs2 : g_offs1;
    int* pos  = blockIdx.x ? g_pos2  : g_pos1;
    __shared__ int wsum[32];
    __shared__ int srun;
    int tid = threadIdx.x, lane = tid & 31, wid = tid >> 5;
    if (tid == 0) srun = 0;
    __syncthreads();
    for (int base = 0; base < NN; base += 1024) {
        int i = base + tid;
        int v = (i < NN) ? cnt[i] : 0;
        int x = v;
#pragma unroll
        for (int d = 1; d < 32; d <<= 1) {
            int y = __shfl_up_sync(0xffffffffu, x, d);
            if (lane >= d) x += y;
        }
        if (lane == 31) wsum[wid] = x;
        __syncthreads();
        if (wid == 0) {
            int w = wsum[lane];
#pragma unroll
            for (int d = 1; d < 32; d <<= 1) {
                int y = __shfl_up_sync(0xffffffffu, w, d);
                if (lane >= d) w += y;
            }
            wsum[lane] = w;
        }
        __syncthreads();
        int pre = (wid > 0) ? wsum[wid - 1] : 0;
        int excl = x - v + pre;
        int run = srun;
        if (i < NN) { offs[i] = run + excl; pos[i] = run + excl; }
        int total = wsum[31];
        __syncthreads();
        if (tid == 0) srun = run + total;
        __syncthreads();
    }
    if (threadIdx.x == 0) offs[NN] = srun;
}

// permute: one thread per edge; sequential reads, random 64B writes
__global__ void __launch_bounds__(256) permute_kernel(
    const float* __restrict__ ea1, const int* __restrict__ row1,
    const int* __restrict__ col1,
    const float* __restrict__ ea2, const int* __restrict__ row2,
    const int* __restrict__ col2)
{
    int r_sel = blockIdx.x & 1;
    const float* ea  = r_sel ? ea2  : ea1;
    const int*   row = r_sel ? row2 : row1;
    const int*   col = r_sel ? col2 : col1;
    int*   pos  = r_sel ? g_pos2  : g_pos1;
    float* eap  = r_sel ? g_eap2  : g_eap1;
    int*   rowp = r_sel ? g_rowp2 : g_rowp1;
    int stride = (gridDim.x >> 1) * blockDim.x;
    for (int e = (blockIdx.x >> 1) * blockDim.x + threadIdx.x; e < EE; e += stride) {
        int c = __ldg(col + e);
        int p = atomicAdd(&pos[c], 1);
        const float4* src = reinterpret_cast<const float4*>(ea + (size_t)e * 16);
        float4* dst = reinterpret_cast<float4*>(eap + (size_t)p * 16);
        dst[0] = __ldg(src);
        dst[1] = __ldg(src + 1);
        dst[2] = __ldg(src + 2);
        dst[3] = __ldg(src + 3);
        rowp[p] = __ldg(row + e);
    }
}

// ---------------- projection (R11-best): one matrix per block --------------
__global__ void __launch_bounds__(128, 4) proj_kernel(
    const float* __restrict__ x_a,
    const float* __restrict__ Wq_a, const float* __restrict__ Wk_a,
    const float* __restrict__ Wv_a,
    const float* __restrict__ emb_a, const float* __restrict__ rel_a,
    float* __restrict__ SQ_a, float* __restrict__ SK_a, float* __restrict__ vp_a,
    const float* __restrict__ x_b,
    const float* __restrict__ Wq_b, const float* __restrict__ Wk_b,
    const float* __restrict__ Wv_b,
    const float* __restrict__ emb_b, const float* __restrict__ rel_b,
    float* __restrict__ SQ_b, float* __restrict__ SK_b, float* __restrict__ vp_b,
    const float* __restrict__ a_attn, int pb)
{
    int bix = blockIdx.x;
    int typ = (bix >= 3 * pb);
    int rem = typ ? (bix - 3 * pb) : bix;
    int mat = rem / pb;
    int blk = rem - mat * pb;

    const float* x   = typ ? x_b   : x_a;
    const float* emb = typ ? emb_b : emb_a;
    const float* rel = typ ? rel_b : rel_a;
    const float* W;
    if (mat == 0)      W = typ ? Wq_b : Wq_a;
    else if (mat == 1) W = typ ? Wk_b : Wk_a;
    else               W = typ ? Wv_b : Wv_a;

    __shared__ float sW[64 * 64];
    __shared__ float xT[64 * 129];

    int tid = threadIdx.x;
    int half = tid >> 6;
    int pr   = tid & 63;
    int node0 = blk * 128;

    {
        const float4* W4 = reinterpret_cast<const float4*>(W);
        float4* s4 = reinterpret_cast<float4*>(sW);
#pragma unroll
        for (int i = 0; i < 8; i++) s4[tid + 128 * i] = W4[tid + 128 * i];
    }
    for (int i = tid; i < 128 * 64; i += 128) {
        int rrow = i >> 6;
        int ccol = i & 63;
        int gn = node0 + rrow;
        float v = (gn < NN) ? __ldg(x + gn * 64 + ccol) : 0.f;
        xT[ccol * 129 + rrow] = v;
    }
    __syncthreads();

    u64 acc0[16], acc1[16];
#pragma unroll
    for (int p = 0; p < 16; p++) { acc0[p] = 0; acc1[p] = 0; }

#pragma unroll 4
    for (int k = 0; k < 64; k++) {
        float xs0 = xT[k * 129 + pr];
        float xs1 = xT[k * 129 + pr + 64];
        u64 xp0 = pack2(xs0, xs0);
        u64 xp1 = pack2(xs1, xs1);
        const ulonglong2* wrow =
            reinterpret_cast<const ulonglong2*>(sW + k * 64 + half * 32);
#pragma unroll
        for (int m = 0; m < 8; m++) {
            ulonglong2 w = wrow[m];
            ffma2(acc0[2 * m],     xp0, w.x);
            ffma2(acc0[2 * m + 1], xp0, w.y);
            ffma2(acc1[2 * m],     xp1, w.x);
            ffma2(acc1[2 * m + 1], xp1, w.y);
        }
    }

    if (mat < 2) {
        const float* aa = a_attn + mat * 32;
        const float* eb = emb + half * 32;
        float s0 = 0.f, s1 = 0.f;
#pragma unroll
        for (int p = 0; p < 16; p++) {
            float e0 = __ldg(eb + 2 * p);
            float e1 = __ldg(eb + 2 * p + 1);
            float a0 = __ldg(aa + 2 * p);
            float a1 = __ldg(aa + 2 * p + 1);
            float f0, f1, g0, g1;
            unpack2(acc0[p], f0, f1);
            unpack2(acc1[p], g0, g1);
            s0 = fmaf(tanh_h(f0 + e0), a0, s0);
            s0 = fmaf(tanh_h(f1 + e1), a1, s0);
            s1 = fmaf(tanh_h(g0 + e0), a0, s1);
            s1 = fmaf(tanh_h(g1 + e1), a1, s1);
        }
        float* outp = (mat == 0) ? (typ ? SQ_b : SQ_a) : (typ ? SK_b : SK_a);
        int gn0 = node0 + pr;
        int gn1 = node0 + pr + 64;
        if (gn0 < NN) outp[gn0 * 2 + half] = s0;
        if (gn1 < NN) outp[gn1 * 2 + half] = s1;
    } else {
        const float* rl = rel + half * 32;
        __syncthreads();
#pragma unroll
        for (int p = 0; p < 16; p++) {
            float r0 = __ldg(rl + 2 * p);
            float r1 = __ldg(rl + 2 * p + 1);
            float f0, f1, g0, g1;
            unpack2(acc0[p], f0, f1);
            unpack2(acc1[p], g0, g1);
            int j0 = half * 32 + 2 * p;
            xT[j0 * 129 + pr]            = f0 + r0;
            xT[(j0 + 1) * 129 + pr]      = f1 + r1;
            xT[j0 * 129 + pr + 64]       = g0 + r0;
            xT[(j0 + 1) * 129 + pr + 64] = g1 + r1;
        }
        __syncthreads();
        float* vp = typ ? vp_b : vp_a;
        for (int i = tid; i < 128 * 64; i += 128) {
            int nl = i >> 6;
            int col = i & 63;
            int gn = node0 + nl;
            if (gn < NN) vp[gn * 64 + col] = xT[col * 129 + nl];
        }
    }
}

// ---------------- aggregation: half-warp per dest node, sequential ea ------
// No atomics, register accumulation, sequential ea_perm stream.
__global__ void __launch_bounds__(256, 4) agg_kernel(
    const float* __restrict__ SQ1, const float* __restrict__ SK1,
    const float* __restrict__ vp1,
    float* __restrict__ s1, float* __restrict__ agg1,
    const float* __restrict__ rel1,
    const float* __restrict__ SQ2, const float* __restrict__ SK2,
    const float* __restrict__ vp2,
    float* __restrict__ s2, float* __restrict__ agg2,
    const float* __restrict__ rel2,
    const float* __restrict__ a_attn, const float* __restrict__ We)
{
    __shared__ float4 sWe[256];
    int tid = threadIdx.x;
    sWe[tid] = reinterpret_cast<const float4*>(We)[tid];
    __syncthreads();

    int r_sel = blockIdx.x & 1;
    const float* eap  = r_sel ? g_eap2  : g_eap1;
    const int*   rowp = r_sel ? g_rowp2 : g_rowp1;
    const int*   offs = r_sel ? g_offs2 : g_offs1;
    const float* SQd  = r_sel ? SQ2 : SQ1;
    const float* SKs  = r_sel ? SK2 : SK1;
    const float* vps  = r_sel ? vp2 : vp1;
    float*       s    = r_sel ? s2  : s1;
    float*       agg  = r_sel ? agg2 : agg1;
    const float* relv = r_sel ? rel2 : rel1;

    int lane = tid & 31;
    int l = lane & 15;
    int sub = lane >> 4;
    int h = l >> 3;
    unsigned hm8 = 0xffu << (lane & 24);

    int gw = (((blockIdx.x >> 1) * blockDim.x) + tid) >> 5;
    int nw = ((gridDim.x >> 1) * blockDim.x) >> 5;

    float4 ae = __ldg(reinterpret_cast<const float4*>(a_attn + 96) + (l & 7));
    float4 r4 = __ldg(reinterpret_cast<const float4*>(relv) + l);
    float cc = tanh_h(r4.x) * ae.x + tanh_h(r4.y) * ae.y
             + tanh_h(r4.z) * ae.z + tanh_h(r4.w) * ae.w;
    cc += __shfl_xor_sync(hm8, cc, 4);
    cc += __shfl_xor_sync(hm8, cc, 2);
    cc += __shfl_xor_sync(hm8, cc, 1);

    const ulonglong2* sWe2 = reinterpret_cast<const ulonglong2*>(sWe);

    for (int np = gw; np < NN / 2; np += nw) {
        int n = 2 * np + sub;
        int beg = __ldg(offs + n);
        int end = __ldg(offs + n + 1);
        float sq = __ldg(SQd + 2 * n + h);

        float4 acc = make_float4(0.f, 0.f, 0.f, 0.f);
        float sacc = 0.f;

#pragma unroll 2
        for (int j = beg; j < end; j++) {
            int r = __ldg(rowp + j);                       // sequential
            float skv = __ldg(SKs + 2 * r + h);
            float4 v4 = __ldg(reinterpret_cast<const float4*>(vps + r * 64) + l);

            const float4* ep4 = reinterpret_cast<const float4*>(eap + (size_t)j * 16);
            float4 A = __ldg(ep4), B = __ldg(ep4 + 1);     // sequential
            float4 C4 = __ldg(ep4 + 2), D = __ldg(ep4 + 3);
            float eav[16] = {A.x, A.y, A.z, A.w, B.x, B.y, B.z, B.w,
                             C4.x, C4.y, C4.z, C4.w, D.x, D.y, D.z, D.w};

            u64 eb01 = 0, eb23 = 0;
#pragma unroll
            for (int k = 0; k < 16; k++) {
                u64 pk = pack2(eav[k], eav[k]);
                ulonglong2 w = sWe2[k * 16 + l];
                ffma2(eb01, pk, w.x);
                ffma2(eb23, pk, w.y);
            }
            float ebx, eby, ebz, ebw;
            unpack2(eb01, ebx, eby);
            unpack2(eb23, ebz, ebw);

            float se = tanh_h(ebx) * ae.x + tanh_h(eby) * ae.y
                     + tanh_h(ebz) * ae.z + tanh_h(ebw) * ae.w;
            se += __shfl_xor_sync(hm8, se, 4);
            se += __shfl_xor_sync(hm8, se, 2);
            se += __shfl_xor_sync(hm8, se, 1);

            float score = se + cc + sq + skv;
            float ex = __expf(score);

            acc.x = fmaf(v4.x + ebx, ex, acc.x);
            acc.y = fmaf(v4.y + eby, ex, acc.y);
            acc.z = fmaf(v4.z + ebz, ex, acc.z);
            acc.w = fmaf(v4.w + ebw, ex, acc.w);
            sacc += ex;
        }

        *reinterpret_cast<float4*>(agg + n * 64 + 4 * l) = acc;
        if ((l & 7) == 0) s[2 * n + h] = sacc;
    }
}

// ---------------- epilogue: fin = (agg/s)@Wo + bo + x@Wr -------------------
__global__ void __launch_bounds__(128) final_kernel(
    const float* __restrict__ agg_a, const float* __restrict__ s_a,
    const float* __restrict__ x_a,
    const float* __restrict__ Wo_a, const float* __restrict__ bo_a,
    const float* __restrict__ Wr_a,
    const float* __restrict__ agg_b, const float* __restrict__ s_b,
    const float* __restrict__ x_b,
    const float* __restrict__ Wo_b, const float* __restrict__ bo_b,
    const float* __restrict__ Wr_b,
    float* __restrict__ out, int pb)
{
    int typ = (blockIdx.x >= pb);
    int blk = typ ? (blockIdx.x - pb) : blockIdx.x;
    const float* agg = typ ? agg_b : agg_a;
    const float* s   = typ ? s_b   : s_a;
    const float* x   = typ ? x_b   : x_a;
    const float* Wo  = typ ? Wo_b  : Wo_a;
    const float* bo  = typ ? bo_b  : bo_a;
    const float* Wr  = typ ? Wr_b  : Wr_a;
    float* outp = out + (typ ? NN * 32 : 0);

    __shared__ float W2[128 * 32];
    __shared__ float sbo[32];
    int tid = threadIdx.x;
    for (int i = tid; i < 2048; i += 128) {
        W2[i]        = Wo[i];
        W2[2048 + i] = Wr[i];
    }
    if (tid < 32) sbo[tid] = bo[tid];
    __syncthreads();

    int node = blk * 128 + tid;
    if (node >= NN) return;

    float s0 = __ldg(s + node * 2);
    float s1 = __ldg(s + node * 2 + 1);
    float i0 = (s0 != 0.f) ? __fdividef(1.f, s0) : 0.f;
    float i1 = (s1 != 0.f) ? __fdividef(1.f, s1) : 0.f;
    u64 inv0p = pack2(i0, i0);
    u64 inv1p = pack2(i1, i1);

    u64 acc[16];
#pragma unroll
    for (int p = 0; p < 16; p++) acc[p] = pack2(sbo[2 * p], sbo[2 * p + 1]);

    const float4* ap = reinterpret_cast<const float4*>(agg + node * 64);
    const float4* xp = reinterpret_cast<const float4*>(x + node * 64);

#pragma unroll 1
    for (int t = 0; t < 16; t++) {
        float4 b0, b1;
        if (t < 8) { b0 = __ldg(ap + 2 * t);       b1 = __ldg(ap + 2 * t + 1); }
        else       { b0 = __ldg(xp + 2 * (t - 8)); b1 = __ldg(xp + 2 * (t - 8) + 1); }
        float bv[8] = {b0.x, b0.y, b0.z, b0.w, b1.x, b1.y, b1.z, b1.w};
        bool is_agg = (t < 8);
        u64 invp = (t < 4) ? inv0p : inv1p;
#pragma unroll
        for (int kk = 0; kk < 8; kk++) {
            u64 cp = pack2(bv[kk], bv[kk]);
            if (is_agg) cp = mul2(cp, invp);
            const ulonglong2* wr = reinterpret_cast<const ulonglong2*>(W2 + (t * 8 + kk) * 32);
#pragma unroll
            for (int p2 = 0; p2 < 8; p2++) {
                ulonglong2 wv = wr[p2];
                ffma2(acc[2 * p2], cp, wv.x);
                ffma2(acc[2 * p2 + 1], cp, wv.y);
            }
        }
    }

    float* op = outp + node * 32;
#pragma unroll
    for (int q = 0; q < 8; q++) {
        float4 o4;
        unpack2(acc[2 * q], o4.x, o4.y);
        unpack2(acc[2 * q + 1], o4.z, o4.w);
        *reinterpret_cast<float4*>(op + 4 * q) = o4;
    }
}

// ---------------- launch ---------------------------------------------------
extern "C" void kernel_launch(void* const* d_in, const int* in_sizes, int n_in,
                              void* d_out, int out_size) {
    const float* x_a   = (const float*)d_in[0];
    const float* x_b   = (const float*)d_in[1];
    const float* ea1   = (const float*)d_in[2];
    const float* ea2   = (const float*)d_in[3];
    const float* Wq_a  = (const float*)d_in[4];
    const float* Wk_a  = (const float*)d_in[5];
    const float* Wv_a  = (const float*)d_in[6];
    const float* Wq_b  = (const float*)d_in[7];
    const float* Wk_b  = (const float*)d_in[8];
    const float* Wv_b  = (const float*)d_in[9];
    const float* emb_a = (const float*)d_in[10];
    const float* emb_b = (const float*)d_in[11];
    const float* rel1  = (const float*)d_in[12];
    const float* rel2  = (const float*)d_in[13];
    const float* We    = (const float*)d_in[14];
    const float* a_at  = (const float*)d_in[15];
    const float* Wo_a  = (const float*)d_in[16];
    const float* bo_a  = (const float*)d_in[17];
    const float* Wo_b  = (const float*)d_in[18];
    const float* bo_b  = (const float*)d_in[19];
    const float* Wr_a  = (const float*)d_in[20];
    const float* Wr_b  = (const float*)d_in[21];
    const int*   row1  = (const int*)d_in[22];
    const int*   col1  = (const int*)d_in[23];
    const int*   row2  = (const int*)d_in[24];
    const int*   col2  = (const int*)d_in[25];
    float* out = (float*)d_out;

    void *pSQa, *pSKa, *pSQb, *pSKb, *pvpa, *pvpb, *psa, *psb, *pagga, *paggb;
    void *pcnt1, *pcnt2;
    cudaGetSymbolAddress(&pSQa, g_SQa);
    cudaGetSymbolAddress(&pSKa, g_SKa);
    cudaGetSymbolAddress(&pSQb, g_SQb);
    cudaGetSymbolAddress(&pSKb, g_SKb);
    cudaGetSymbolAddress(&pvpa, g_vpa);
    cudaGetSymbolAddress(&pvpb, g_vpb);
    cudaGetSymbolAddress(&psa, g_sa);
    cudaGetSymbolAddress(&psb, g_sb);
    cudaGetSymbolAddress(&pagga, g_agga);
    cudaGetSymbolAddress(&paggb, g_aggb);
    cudaGetSymbolAddress(&pcnt1, g_cnt1);
    cudaGetSymbolAddress(&pcnt2, g_cnt2);

    // CSR build + permutation
    cudaMemsetAsync(pcnt1, 0, sizeof(int) * NN);
    cudaMemsetAsync(pcnt2, 0, sizeof(int) * NN);
    hist_kernel<<<512, 256>>>(col1, col2);
    scan_kernel<<<2, 1024>>>();
    permute_kernel<<<1024, 256>>>(ea1, row1, col1, ea2, row2, col2);

    int pb = (NN + 127) / 128;
    proj_kernel<<<6 * pb, 128>>>(
        x_a, Wq_a, Wk_a, Wv_a, emb_a, rel1,
        (float*)pSQa, (float*)pSKa, (float*)pvpa,
        x_b, Wq_b, Wk_b, Wv_b, emb_b, rel2,
        (float*)pSQb, (float*)pSKb, (float*)pvpb,
        a_at, pb);

    // relation1 (even blocks): a -> b (dst=b); relation2 (odd): b -> a (dst=a)
    agg_kernel<<<2048, 256>>>(
        (const float*)pSQb, (const float*)pSKa, (const float*)pvpa,
        (float*)psb, (float*)paggb, rel1,
        (const float*)pSQa, (const float*)pSKb, (const float*)pvpb,
        (float*)psa, (float*)pagga, rel2,
        a_at, We);

    final_kernel<<<2 * pb, 128>>>(
        (const float*)pagga, (const float*)psa, x_a, Wo_a, bo_a, Wr_a,
        (const float*)paggb, (const float*)psb, x_b, Wo_b, bo_b, Wr_b,
        out, pb);
}

// round 17
// speedup vs baseline: 2.2245x; 2.2245x over previous
#include <cuda_runtime.h>

#define NN 50000
#define EE 800000

typedef unsigned long long u64;

// ---------------- scratch (device globals; no allocation allowed) ----------
__device__ float g_SQa[NN * 2];
__device__ float g_SKa[NN * 2];
__device__ float g_SQb[NN * 2];
__device__ float g_SKb[NN * 2];
__device__ float g_vpa[NN * 64];
__device__ float g_vpb[NN * 64];
__device__ float g_sa[NN * 2];
__device__ float g_sb[NN * 2];
__device__ float g_agga[NN * 64];
__device__ float g_aggb[NN * 64];

__device__ __forceinline__ float tanh_h(float x) {
    float y;
    asm("tanh.approx.f32 %0, %1;" : "=f"(y) : "f"(x));
    return y;
}
__device__ __forceinline__ void red_add_v4(float* p, float4 v) {
    asm volatile("red.global.add.v4.f32 [%0], {%1, %2, %3, %4};"
                 :: "l"(p), "f"(v.x), "f"(v.y), "f"(v.z), "f"(v.w) : "memory");
}
__device__ __forceinline__ u64 pack2(float a, float b) {
    u64 r;
    asm("mov.b64 %0, {%1, %2};" : "=l"(r) : "f"(a), "f"(b));
    return r;
}
__device__ __forceinline__ void unpack2(u64 v, float& a, float& b) {
    asm("mov.b64 {%0, %1}, %2;" : "=f"(a), "=f"(b) : "l"(v));
}
__device__ __forceinline__ void ffma2(u64& d, u64 a, u64 b) {
    asm("fma.rn.f32x2 %0, %1, %2, %3;" : "=l"(d) : "l"(a), "l"(b), "l"(d));
}
__device__ __forceinline__ u64 mul2(u64 a, u64 b) {
    u64 r;
    asm("mul.rn.f32x2 %0, %1, %2;" : "=l"(r) : "l"(a), "l"(b));
    return r;
}

// ---------------- projection (R11-best) + scratch zeroing ------------------
// mat 0: SQ (+ zero s of the relation where this type is DST)
// mat 1: SK
// mat 2: vp (+ zero agg rows for this type)
__global__ void __launch_bounds__(128, 4) proj_kernel(
    const float* __restrict__ x_a,
    const float* __restrict__ Wq_a, const float* __restrict__ Wk_a,
    const float* __restrict__ Wv_a,
    const float* __restrict__ emb_a, const float* __restrict__ rel_a,
    float* __restrict__ SQ_a, float* __restrict__ SK_a, float* __restrict__ vp_a,
    float* __restrict__ s_a, float* __restrict__ agg_a,
    const float* __restrict__ x_b,
    const float* __restrict__ Wq_b, const float* __restrict__ Wk_b,
    const float* __restrict__ Wv_b,
    const float* __restrict__ emb_b, const float* __restrict__ rel_b,
    float* __restrict__ SQ_b, float* __restrict__ SK_b, float* __restrict__ vp_b,
    float* __restrict__ s_b, float* __restrict__ agg_b,
    const float* __restrict__ a_attn, int pb)
{
    int bix = blockIdx.x;
    int typ = (bix >= 3 * pb);
    int rem = typ ? (bix - 3 * pb) : bix;
    int mat = rem / pb;
    int blk = rem - mat * pb;

    const float* x   = typ ? x_b   : x_a;
    const float* emb = typ ? emb_b : emb_a;
    const float* rel = typ ? rel_b : rel_a;
    const float* W;
    if (mat == 0)      W = typ ? Wq_b : Wq_a;
    else if (mat == 1) W = typ ? Wk_b : Wk_a;
    else               W = typ ? Wv_b : Wv_a;

    __shared__ float sW[64 * 64];        // 16KB
    __shared__ float xT[64 * 129];       // ~33KB, transposed + pad 129

    int tid = threadIdx.x;
    int half = tid >> 6;
    int pr   = tid & 63;
    int node0 = blk * 128;

    {
        const float4* W4 = reinterpret_cast<const float4*>(W);
        float4* s4 = reinterpret_cast<float4*>(sW);
#pragma unroll
        for (int i = 0; i < 8; i++) s4[tid + 128 * i] = W4[tid + 128 * i];
    }
    for (int i = tid; i < 128 * 64; i += 128) {
        int rrow = i >> 6;
        int ccol = i & 63;
        int gn = node0 + rrow;
        float v = (gn < NN) ? __ldg(x + gn * 64 + ccol) : 0.f;
        xT[ccol * 129 + rrow] = v;
    }
    // mat 2 blocks also zero this type's agg rows (coalesced, independent)
    if (mat == 2) {
        float* agg = typ ? agg_b : agg_a;
        float4 z = make_float4(0.f, 0.f, 0.f, 0.f);
        for (int i = tid; i < 128 * 16; i += 128) {
            int gn = node0 + (i >> 4);
            if (gn < NN)
                reinterpret_cast<float4*>(agg + gn * 64)[i & 15] = z;
        }
    }
    __syncthreads();

    int node = node0 + tid;  // (unused; kept for clarity of tile extent)
    (void)node;

    u64 acc0[16], acc1[16];
#pragma unroll
    for (int p = 0; p < 16; p++) { acc0[p] = 0; acc1[p] = 0; }

#pragma unroll 4
    for (int k = 0; k < 64; k++) {
        float xs0 = xT[k * 129 + pr];
        float xs1 = xT[k * 129 + pr + 64];
        u64 xp0 = pack2(xs0, xs0);
        u64 xp1 = pack2(xs1, xs1);
        const ulonglong2* wrow =
            reinterpret_cast<const ulonglong2*>(sW + k * 64 + half * 32);
#pragma unroll
        for (int m = 0; m < 8; m++) {
            ulonglong2 w = wrow[m];
            ffma2(acc0[2 * m],     xp0, w.x);
            ffma2(acc0[2 * m + 1], xp0, w.y);
            ffma2(acc1[2 * m],     xp1, w.x);
            ffma2(acc1[2 * m + 1], xp1, w.y);
        }
    }

    if (mat < 2) {
        const float* aa = a_attn + mat * 32;
        const float* eb = emb + half * 32;
        float s0 = 0.f, s1 = 0.f;
#pragma unroll
        for (int p = 0; p < 16; p++) {
            float e0 = __ldg(eb + 2 * p);
            float e1 = __ldg(eb + 2 * p + 1);
            float a0 = __ldg(aa + 2 * p);
            float a1 = __ldg(aa + 2 * p + 1);
            float f0, f1, g0, g1;
            unpack2(acc0[p], f0, f1);
            unpack2(acc1[p], g0, g1);
            s0 = fmaf(tanh_h(f0 + e0), a0, s0);
            s0 = fmaf(tanh_h(f1 + e1), a1, s0);
            s1 = fmaf(tanh_h(g0 + e0), a0, s1);
            s1 = fmaf(tanh_h(g1 + e1), a1, s1);
        }
        float* outp = (mat == 0) ? (typ ? SQ_b : SQ_a) : (typ ? SK_b : SK_a);
        int gn0 = node0 + pr;
        int gn1 = node0 + pr + 64;
        if (gn0 < NN) outp[gn0 * 2 + half] = s0;
        if (gn1 < NN) outp[gn1 * 2 + half] = s1;
        // mat 0 blocks zero the softmax-denominator array of this type
        // (type is DST of the relation using its SQ)
        if (mat == 0) {
            float* sz = typ ? s_b : s_a;
            if (gn0 < NN) sz[gn0 * 2 + half] = 0.f;
            if (gn1 < NN) sz[gn1 * 2 + half] = 0.f;
        }
    } else {
        const float* rl = rel + half * 32;
        __syncthreads();
#pragma unroll
        for (int p = 0; p < 16; p++) {
            float r0 = __ldg(rl + 2 * p);
            float r1 = __ldg(rl + 2 * p + 1);
            float f0, f1, g0, g1;
            unpack2(acc0[p], f0, f1);
            unpack2(acc1[p], g0, g1);
            int j0 = half * 32 + 2 * p;
            xT[j0 * 129 + pr]            = f0 + r0;
            xT[(j0 + 1) * 129 + pr]      = f1 + r1;
            xT[j0 * 129 + pr + 64]       = g0 + r0;
            xT[(j0 + 1) * 129 + pr + 64] = g1 + r1;
        }
        __syncthreads();
        float* vp = typ ? vp_b : vp_a;
        for (int i = tid; i < 128 * 64; i += 128) {
            int nl = i >> 6;
            int col = i & 63;
            int gn = node0 + nl;
            if (gn < NN) vp[gn * 64 + col] = xT[col * 129 + nl];
        }
    }
}

// ---------------- edge pass (R13-best): half-warp per edge, f32x2 GEMM -----
__global__ void __launch_bounds__(256, 5) edge_kernel(
    const float* __restrict__ ea1,
    const int* __restrict__ row1, const int* __restrict__ col1,
    const float* __restrict__ SQ1, const float* __restrict__ SK1,
    const float* __restrict__ vp1,
    float* __restrict__ s1, float* __restrict__ agg1,
    const float* __restrict__ rel1,
    const float* __restrict__ ea2,
    const int* __restrict__ row2, const int* __restrict__ col2,
    const float* __restrict__ SQ2, const float* __restrict__ SK2,
    const float* __restrict__ vp2,
    float* __restrict__ s2, float* __restrict__ agg2,
    const float* __restrict__ rel2,
    const float* __restrict__ a_attn, const float* __restrict__ We)
{
    __shared__ float4 sWe[256];  // We as 16 rows x 16 float4 (64 ch)
    int tid = threadIdx.x;
    sWe[tid] = reinterpret_cast<const float4*>(We)[tid];
    __syncthreads();

    int r_sel = blockIdx.x & 1;
    const float* ea  = r_sel ? ea2  : ea1;
    const int*   row = r_sel ? row2 : row1;
    const int*   col = r_sel ? col2 : col1;
    const float* SQd = r_sel ? SQ2 : SQ1;
    const float* SKs = r_sel ? SK2 : SK1;
    const float* vps = r_sel ? vp2 : vp1;
    float*       s   = r_sel ? s2  : s1;
    float*       agg = r_sel ? agg2 : agg1;
    const float* relv = r_sel ? rel2 : rel1;

    int lane = tid & 31;
    int l = lane & 15;
    int sub = lane >> 4;
    int h = l >> 3;

    int gw = (((blockIdx.x >> 1) * blockDim.x) + tid) >> 5;
    int nw = ((gridDim.x >> 1) * blockDim.x) >> 5;

    float4 ae = __ldg(reinterpret_cast<const float4*>(a_attn + 96) + (l & 7));
    float4 r4 = __ldg(reinterpret_cast<const float4*>(relv) + l);
    float cc = tanh_h(r4.x) * ae.x + tanh_h(r4.y) * ae.y
             + tanh_h(r4.z) * ae.z + tanh_h(r4.w) * ae.w;
    cc += __shfl_xor_sync(0xffffffffu, cc, 4);
    cc += __shfl_xor_sync(0xffffffffu, cc, 2);
    cc += __shfl_xor_sync(0xffffffffu, cc, 1);

    const ulonglong2* sWe2 = reinterpret_cast<const ulonglong2*>(sWe);

    for (int ep = gw; ep < EE / 2; ep += nw) {
        int e = ep * 2 + sub;
        int r = __ldg(row + e);
        int c = __ldg(col + e);

        const float4* eap = reinterpret_cast<const float4*>(ea + (size_t)e * 16);
        float4 A = __ldg(eap), B = __ldg(eap + 1), C4 = __ldg(eap + 2), D = __ldg(eap + 3);
        float eav[16] = {A.x, A.y, A.z, A.w, B.x, B.y, B.z, B.w,
                         C4.x, C4.y, C4.z, C4.w, D.x, D.y, D.z, D.w};

        u64 eb01 = 0, eb23 = 0;
#pragma unroll
        for (int k = 0; k < 16; k++) {
            u64 pk = pack2(eav[k], eav[k]);
            ulonglong2 w = sWe2[k * 16 + l];
            ffma2(eb01, pk, w.x);
            ffma2(eb23, pk, w.y);
        }
        float ebx, eby, ebz, ebw;
        unpack2(eb01, ebx, eby);
        unpack2(eb23, ebz, ebw);

        float se = tanh_h(ebx) * ae.x + tanh_h(eby) * ae.y
                 + tanh_h(ebz) * ae.z + tanh_h(ebw) * ae.w;
        se += __shfl_xor_sync(0xffffffffu, se, 4);
        se += __shfl_xor_sync(0xffffffffu, se, 2);
        se += __shfl_xor_sync(0xffffffffu, se, 1);

        float score = se + cc + __ldg(SQd + 2 * c + h) + __ldg(SKs + 2 * r + h);
        float ex = __expf(score);

        float4 v4 = __ldg(reinterpret_cast<const float4*>(vps + r * 64) + l);
        float4 m;
        m.x = (v4.x + ebx) * ex;
        m.y = (v4.y + eby) * ex;
        m.z = (v4.z + ebz) * ex;
        m.w = (v4.w + ebw) * ex;

        red_add_v4(agg + c * 64 + 4 * l, m);
        if ((l & 7) == 0) atomicAdd(s + 2 * c + h, ex);
    }
}

// ---------------- epilogue: fin = (agg/s)@Wo + bo + x@Wr -------------------
__global__ void __launch_bounds__(128) final_kernel(
    const float* __restrict__ agg_a, const float* __restrict__ s_a,
    const float* __restrict__ x_a,
    const float* __restrict__ Wo_a, const float* __restrict__ bo_a,
    const float* __restrict__ Wr_a,
    const float* __restrict__ agg_b, const float* __restrict__ s_b,
    const float* __restrict__ x_b,
    const float* __restrict__ Wo_b, const float* __restrict__ bo_b,
    const float* __restrict__ Wr_b,
    float* __restrict__ out, int pb)
{
    int typ = (blockIdx.x >= pb);
    int blk = typ ? (blockIdx.x - pb) : blockIdx.x;
    const float* agg = typ ? agg_b : agg_a;
    const float* s   = typ ? s_b   : s_a;
    const float* x   = typ ? x_b   : x_a;
    const float* Wo  = typ ? Wo_b  : Wo_a;
    const float* bo  = typ ? bo_b  : bo_a;
    const float* Wr  = typ ? Wr_b  : Wr_a;
    float* outp = out + (typ ? NN * 32 : 0);

    __shared__ float W2[128 * 32];
    __shared__ float sbo[32];
    int tid = threadIdx.x;
    for (int i = tid; i < 2048; i += 128) {
        W2[i]        = Wo[i];
        W2[2048 + i] = Wr[i];
    }
    if (tid < 32) sbo[tid] = bo[tid];
    __syncthreads();

    int node = blk * 128 + tid;
    if (node >= NN) return;

    float s0 = __ldg(s + node * 2);
    float s1 = __ldg(s + node * 2 + 1);
    float i0 = (s0 != 0.f) ? __fdividef(1.f, s0) : 0.f;
    float i1 = (s1 != 0.f) ? __fdividef(1.f, s1) : 0.f;
    u64 inv0p = pack2(i0, i0);
    u64 inv1p = pack2(i1, i1);

    u64 acc[16];
#pragma unroll
    for (int p = 0; p < 16; p++) acc[p] = pack2(sbo[2 * p], sbo[2 * p + 1]);

    const float4* ap = reinterpret_cast<const float4*>(agg + node * 64);
    const float4* xp = reinterpret_cast<const float4*>(x + node * 64);

#pragma unroll 1
    for (int t = 0; t < 16; t++) {
        float4 b0, b1;
        if (t < 8) { b0 = __ldg(ap + 2 * t);       b1 = __ldg(ap + 2 * t + 1); }
        else       { b0 = __ldg(xp + 2 * (t - 8)); b1 = __ldg(xp + 2 * (t - 8) + 1); }
        float bv[8] = {b0.x, b0.y, b0.z, b0.w, b1.x, b1.y, b1.z, b1.w};
        bool is_agg = (t < 8);
        u64 invp = (t < 4) ? inv0p : inv1p;
#pragma unroll
        for (int kk = 0; kk < 8; kk++) {
            u64 cp = pack2(bv[kk], bv[kk]);
            if (is_agg) cp = mul2(cp, invp);
            const ulonglong2* wr = reinterpret_cast<const ulonglong2*>(W2 + (t * 8 + kk) * 32);
#pragma unroll
            for (int p2 = 0; p2 < 8; p2++) {
                ulonglong2 wv = wr[p2];
                ffma2(acc[2 * p2], cp, wv.x);
                ffma2(acc[2 * p2 + 1], cp, wv.y);
            }
        }
    }

    float* op = outp + node * 32;
#pragma unroll
    for (int q = 0; q < 8; q++) {
        float4 o4;
        unpack2(acc[2 * q], o4.x, o4.y);
        unpack2(acc[2 * q + 1], o4.z, o4.w);
        *reinterpret_cast<float4*>(op + 4 * q) = o4;
    }
}

// ---------------- launch ---------------------------------------------------
extern "C" void kernel_launch(void* const* d_in, const int* in_sizes, int n_in,
                              void* d_out, int out_size) {
    const float* x_a   = (const float*)d_in[0];
    const float* x_b   = (const float*)d_in[1];
    const float* ea1   = (const float*)d_in[2];
    const float* ea2   = (const float*)d_in[3];
    const float* Wq_a  = (const float*)d_in[4];
    const float* Wk_a  = (const float*)d_in[5];
    const float* Wv_a  = (const float*)d_in[6];
    const float* Wq_b  = (const float*)d_in[7];
    const float* Wk_b  = (const float*)d_in[8];
    const float* Wv_b  = (const float*)d_in[9];
    const float* emb_a = (const float*)d_in[10];
    const float* emb_b = (const float*)d_in[11];
    const float* rel1  = (const float*)d_in[12];
    const float* rel2  = (const float*)d_in[13];
    const float* We    = (const float*)d_in[14];
    const float* a_at  = (const float*)d_in[15];
    const float* Wo_a  = (const float*)d_in[16];
    const float* bo_a  = (const float*)d_in[17];
    const float* Wo_b  = (const float*)d_in[18];
    const float* bo_b  = (const float*)d_in[19];
    const float* Wr_a  = (const float*)d_in[20];
    const float* Wr_b  = (const float*)d_in[21];
    const int*   row1  = (const int*)d_in[22];
    const int*   col1  = (const int*)d_in[23];
    const int*   row2  = (const int*)d_in[24];
    const int*   col2  = (const int*)d_in[25];
    float* out = (float*)d_out;

    void *pSQa, *pSKa, *pSQb, *pSKb, *pvpa, *pvpb, *psa, *psb, *pagga, *paggb;
    cudaGetSymbolAddress(&pSQa, g_SQa);
    cudaGetSymbolAddress(&pSKa, g_SKa);
    cudaGetSymbolAddress(&pSQb, g_SQb);
    cudaGetSymbolAddress(&pSKb, g_SKb);
    cudaGetSymbolAddress(&pvpa, g_vpa);
    cudaGetSymbolAddress(&pvpb, g_vpb);
    cudaGetSymbolAddress(&psa, g_sa);
    cudaGetSymbolAddress(&psb, g_sb);
    cudaGetSymbolAddress(&pagga, g_agga);
    cudaGetSymbolAddress(&paggb, g_aggb);

    int pb = (NN + 127) / 128;
    // proj also zeroes s_a/s_b (mat0 blocks) and agg_a/agg_b (mat2 blocks),
    // so no separate memsets are needed.
    proj_kernel<<<6 * pb, 128>>>(
        x_a, Wq_a, Wk_a, Wv_a, emb_a, rel1,
        (float*)pSQa, (float*)pSKa, (float*)pvpa, (float*)psa, (float*)pagga,
        x_b, Wq_b, Wk_b, Wv_b, emb_b, rel2,
        (float*)pSQb, (float*)pSKb, (float*)pvpb, (float*)psb, (float*)paggb,
        a_at, pb);

    edge_kernel<<<4096, 256>>>(
        ea1, row1, col1, (const float*)pSQb, (const float*)pSKa,
        (const float*)pvpa, (float*)psb, (float*)paggb, rel1,
        ea2, row2, col2, (const float*)pSQa, (const float*)pSKb,
        (const float*)pvpb, (float*)psa, (float*)pagga, rel2,
        a_at, We);

    final_kernel<<<2 * pb, 128>>>(
        (const float*)pagga, (const float*)psa, x_a, Wo_a, bo_a, Wr_a,
        (const float*)paggb, (const float*)psb, x_b, Wo_b, bo_b, Wr_b,
        out, pb);
}